// round 4
// baseline (speedup 1.0000x reference)
#include <cuda_runtime.h>
#include <cuda_bf16.h>

#define BATCH       16
#define N_ROIS      1000
#define NUM_CLASSES 81
#define DET_MAX     100
#define MIN_CONF    0.7f
#define NMS_THRESH  0.3f

__global__ __launch_bounds__(1024, 1)
void DetectionLayer_962072674902_kernel(const float* __restrict__ rois,
                                        const float* __restrict__ probs,
                                        const float* __restrict__ deltas,
                                        const float* __restrict__ window,
                                        float* __restrict__ out)
{
    __shared__ float4       s_box[N_ROIS];
    __shared__ float        s_score[N_ROIS];
    __shared__ int          s_cls[N_ROIS];
    __shared__ int          s_roi[N_ROIS];
    __shared__ int          s_order[N_ROIS];
    __shared__ unsigned char s_sup[N_ROIS];
    __shared__ int          s_klist[DET_MAX];
    __shared__ int          sM, sNK;

    const int b    = blockIdx.x;
    const int tid  = threadIdx.x;
    const int lane = tid & 31;
    const int warp = tid >> 5;

    for (int i = tid; i < N_ROIS; i += 1024) s_sup[i] = 0;
    if (tid == 0) { sM = 0; sNK = 0; }
    __syncthreads();

    const float wy1 = window[b * 4 + 0];
    const float wx1 = window[b * 4 + 1];
    const float wy2 = window[b * 4 + 2];
    const float wx2 = window[b * 4 + 3];

    // ---------------- Phase 1: per-ROI argmax + refine + filter -------------
    // Warp per ROI: 32 warps stride over 1000 ROIs.
    for (int r = warp; r < N_ROIS; r += 32) {
        const float* p = probs + ((size_t)b * N_ROIS + r) * NUM_CLASSES;
        float v0 = p[lane];
        float v1 = p[lane + 32];
        float v2 = (lane < NUM_CLASSES - 64) ? p[lane + 64] : -1e30f;

        // per-lane best (highest value, ties -> lowest class index)
        float bv = v0; int bi = lane;
        if (v1 > bv) { bv = v1; bi = lane + 32; }
        if (v2 > bv) { bv = v2; bi = lane + 64; }
        #pragma unroll
        for (int off = 16; off > 0; off >>= 1) {
            float ov = __shfl_xor_sync(0xffffffffu, bv, off);
            int   oi = __shfl_xor_sync(0xffffffffu, bi, off);
            if (ov > bv || (ov == bv && oi < bi)) { bv = ov; bi = oi; }
        }

        if (lane == 0 && bi > 0 && bv >= MIN_CONF) {
            // gather class-specific deltas (16B aligned float4)
            const float4 d4 = *(const float4*)(deltas +
                (((size_t)b * N_ROIS + r) * NUM_CLASSES + bi) * 4);
            const float4 rb = *(const float4*)(rois +
                ((size_t)b * N_ROIS + r) * 4);

            float h  = rb.z - rb.x;
            float w  = rb.w - rb.y;
            float cy = rb.x + 0.5f * h;
            float cx = rb.y + 0.5f * w;
            cy = cy + (d4.x * 0.1f) * h;
            cx = cx + (d4.y * 0.1f) * w;
            h  = h * expf(d4.z * 0.2f);
            w  = w * expf(d4.w * 0.2f);
            float y1 = cy - 0.5f * h;
            float x1 = cx - 0.5f * w;
            float y2 = y1 + h;
            float x2 = x1 + w;
            // clip to window
            y1 = fminf(fmaxf(y1, wy1), wy2);
            x1 = fminf(fmaxf(x1, wx1), wx2);
            y2 = fminf(fmaxf(y2, wy1), wy2);
            x2 = fminf(fmaxf(x2, wx1), wx2);

            int slot = atomicAdd(&sM, 1);
            s_box[slot]   = make_float4(y1, x1, y2, x2);
            s_score[slot] = bv;
            s_cls[slot]   = bi;
            s_roi[slot]   = r;
        }
    }
    __syncthreads();
    const int M = sM;

    // ---------------- Phase 2: rank sort (score desc, roi idx asc) ---------
    for (int t = tid; t < M; t += 1024) {
        const float st = s_score[t];
        const int   rt = s_roi[t];
        int rank = 0;
        for (int j = 0; j < M; ++j) {
            const float sj = s_score[j];
            if (sj > st || (sj == st && s_roi[j] < rt)) rank++;
        }
        s_order[rank] = t;
    }
    __syncthreads();

    // ---------------- Phase 3: greedy per-class NMS on warp 0 ---------------
    // Class cap (100) can never bind before global cap (100), and kept boxes
    // past 100 global can only suppress lower-scored (never-output) boxes, so
    // terminating at 100 kept is exact.
    if (warp == 0) {
        int nk = 0;
        for (int s = 0; s < M && nk < DET_MAX; ++s) {
            const int ci = s_order[s];
            if (s_sup[ci]) continue;                 // uniform across warp
            if (lane == 0) s_klist[nk] = ci;
            nk++;
            const float4 bi4 = s_box[ci];
            const int    c   = s_cls[ci];
            const float area_i = (bi4.z - bi4.x) * (bi4.w - bi4.y);
            for (int s2 = s + 1 + lane; s2 < M; s2 += 32) {
                const int cj = s_order[s2];
                if (s_cls[cj] != c) continue;
                const float4 bj = s_box[cj];
                const float yy1 = fmaxf(bi4.x, bj.x);
                const float xx1 = fmaxf(bi4.y, bj.y);
                const float yy2 = fminf(bi4.z, bj.z);
                const float xx2 = fminf(bi4.w, bj.w);
                const float inter = fmaxf(yy2 - yy1, 0.0f) * fmaxf(xx2 - xx1, 0.0f);
                const float area_j = (bj.z - bj.x) * (bj.w - bj.y);
                const float uni = fmaxf(area_i + area_j - inter, 1e-10f);
                if (inter / uni > NMS_THRESH) s_sup[cj] = 1;
            }
            __syncwarp();   // make suppress writes visible to next iteration
        }
        if (lane == 0) sNK = nk;
    }
    __syncthreads();

    // ---------------- Phase 4: write [100, 6] output (zero padded) ----------
    const int nk = sNK;
    float* o = out + (size_t)b * DET_MAX * 6;
    for (int t = tid; t < DET_MAX; t += 1024) {
        if (t < nk) {
            const int ci = s_klist[t];
            const float4 bb = s_box[ci];
            o[t * 6 + 0] = bb.x;
            o[t * 6 + 1] = bb.y;
            o[t * 6 + 2] = bb.z;
            o[t * 6 + 3] = bb.w;
            o[t * 6 + 4] = (float)s_cls[ci];
            o[t * 6 + 5] = s_score[ci];
        } else {
            #pragma unroll
            for (int k = 0; k < 6; ++k) o[t * 6 + k] = 0.0f;
        }
    }
}

extern "C" void kernel_launch(void* const* d_in, const int* in_sizes, int n_in,
                              void* d_out, int out_size)
{
    const float* rois   = nullptr;
    const float* probs  = nullptr;
    const float* deltas = nullptr;
    const float* window = nullptr;
    // Identify inputs by element count (all four are distinct).
    for (int i = 0; i < n_in; ++i) {
        switch (in_sizes[i]) {
            case BATCH * N_ROIS * 4:                rois   = (const float*)d_in[i]; break;
            case BATCH * N_ROIS * NUM_CLASSES:      probs  = (const float*)d_in[i]; break;
            case BATCH * N_ROIS * NUM_CLASSES * 4:  deltas = (const float*)d_in[i]; break;
            case BATCH * 4:                         window = (const float*)d_in[i]; break;
        }
    }
    DetectionLayer_962072674902_kernel<<<BATCH, 1024>>>(
        rois, probs, deltas, window, (float*)d_out);
}

// round 5
// speedup vs baseline: 1.5524x; 1.5524x over previous
#include <cuda_runtime.h>
#include <cuda_bf16.h>

#define BATCH       16
#define N_ROIS      1000
#define NUM_CLASSES 81
#define DET_MAX     100
#define MIN_CONF    0.7f
#define NMS_THRESH  0.3f
#define NB_Y        9          // blocks per batch in phase 1 (16*9 = 144 blocks ~ 148 SMs)

// Global scratch (allowed: __device__ globals, no allocation).
// g_cnt is zero-initialized at module load; kernel B resets it after use so
// every graph replay sees the same initial state.
__device__ int   g_cnt[BATCH];
__device__ uint2 g_cand[BATCH * N_ROIS];   // .x = score bits, .y = (roi<<7)|cls

// ---------------------------------------------------------------------------
// Kernel A: per-ROI argmax over 81 classes, compact candidates to global.
// Warp per ROI; 288 warps per batch -> ~3.5 ROIs per warp (fully pipelined).
// ---------------------------------------------------------------------------
__global__ __launch_bounds__(1024, 1)
void det_phase1_kernel(const float* __restrict__ probs)
{
    const int b    = blockIdx.x;
    const int lane = threadIdx.x & 31;
    const int gw   = blockIdx.y * 32 + (threadIdx.x >> 5);   // 0..287

    for (int r = gw; r < N_ROIS; r += 32 * NB_Y) {
        const float* p = probs + ((size_t)b * N_ROIS + r) * NUM_CLASSES;
        const float v0 = p[lane];
        const float v1 = p[lane + 32];
        const float v2 = (lane < NUM_CLASSES - 64) ? p[lane + 64] : -1e30f;

        // per-lane best (highest value, ties -> lowest class index)
        float bv = v0; int bi = lane;
        if (v1 > bv) { bv = v1; bi = lane + 32; }
        if (v2 > bv) { bv = v2; bi = lane + 64; }
        #pragma unroll
        for (int off = 16; off > 0; off >>= 1) {
            const float ov = __shfl_xor_sync(0xffffffffu, bv, off);
            const int   oi = __shfl_xor_sync(0xffffffffu, bi, off);
            if (ov > bv || (ov == bv && oi < bi)) { bv = ov; bi = oi; }
        }

        if (lane == 0 && bi > 0 && bv >= MIN_CONF) {
            const int slot = atomicAdd(&g_cnt[b], 1);
            g_cand[b * N_ROIS + slot] =
                make_uint2(__float_as_uint(bv), ((unsigned)r << 7) | (unsigned)bi);
        }
    }
}

// ---------------------------------------------------------------------------
// Kernel B: refine candidate boxes, sort, greedy per-class NMS, write output.
// One block per batch, 128 threads. Also resets g_cnt for the next replay.
// ---------------------------------------------------------------------------
__global__ __launch_bounds__(128, 1)
void det_phase2_kernel(const float* __restrict__ rois,
                       const float* __restrict__ deltas,
                       const float* __restrict__ window,
                       float* __restrict__ out)
{
    __shared__ float4        s_box[N_ROIS];
    __shared__ float         s_score[N_ROIS];
    __shared__ int           s_cls[N_ROIS];
    __shared__ int           s_roi[N_ROIS];
    __shared__ int           s_order[N_ROIS];
    __shared__ unsigned char s_sup[N_ROIS];
    __shared__ int           s_klist[DET_MAX];
    __shared__ int           sM, sNK;

    const int b    = blockIdx.x;
    const int tid  = threadIdx.x;
    const int lane = tid & 31;
    const int warp = tid >> 5;

    if (tid == 0) { sM = g_cnt[b]; sNK = 0; }
    __syncthreads();
    const int M = sM;
    if (tid == 0) g_cnt[b] = 0;          // reset for next graph replay

    const float wy1 = window[b * 4 + 0];
    const float wx1 = window[b * 4 + 1];
    const float wy2 = window[b * 4 + 2];
    const float wx2 = window[b * 4 + 3];

    // ---- refine + clip candidate boxes (parallel gather, 1-2 round trips) --
    for (int t = tid; t < M; t += 128) {
        const uint2 c  = g_cand[b * N_ROIS + t];
        const float sc = __uint_as_float(c.x);
        const int   r  = (int)(c.y >> 7);
        const int   cl = (int)(c.y & 127u);

        const float4 d4 = *(const float4*)(deltas +
            (((size_t)b * N_ROIS + r) * NUM_CLASSES + cl) * 4);
        const float4 rb = *(const float4*)(rois + ((size_t)b * N_ROIS + r) * 4);

        float h  = rb.z - rb.x;
        float w  = rb.w - rb.y;
        float cy = rb.x + 0.5f * h + (d4.x * 0.1f) * h;
        float cx = rb.y + 0.5f * w + (d4.y * 0.1f) * w;
        h = h * expf(d4.z * 0.2f);
        w = w * expf(d4.w * 0.2f);
        float y1 = cy - 0.5f * h;
        float x1 = cx - 0.5f * w;
        float y2 = y1 + h;
        float x2 = x1 + w;
        y1 = fminf(fmaxf(y1, wy1), wy2);
        x1 = fminf(fmaxf(x1, wx1), wx2);
        y2 = fminf(fmaxf(y2, wy1), wy2);
        x2 = fminf(fmaxf(x2, wx1), wx2);

        s_box[t]   = make_float4(y1, x1, y2, x2);
        s_score[t] = sc;
        s_cls[t]   = cl;
        s_roi[t]   = r;
        s_sup[t]   = 0;
    }
    __syncthreads();

    // ---- rank sort: score desc, roi index asc (total order -> deterministic)
    for (int t = tid; t < M; t += 128) {
        const float st = s_score[t];
        const int   rt = s_roi[t];
        int rank = 0;
        for (int j = 0; j < M; ++j) {
            const float sj = s_score[j];
            if (sj > st || (sj == st && s_roi[j] < rt)) rank++;
        }
        s_order[rank] = t;
    }
    __syncthreads();

    // ---- greedy per-class NMS on warp 0 ------------------------------------
    // Per-class cap (100) can never bind before the global cap (100), and
    // kept boxes past 100 global only suppress lower-scored (never-output)
    // boxes, so terminating at 100 kept is exact.
    if (warp == 0) {
        int nk = 0;
        for (int s = 0; s < M && nk < DET_MAX; ++s) {
            const int ci = s_order[s];
            if (s_sup[ci]) continue;                 // uniform across warp
            if (lane == 0) s_klist[nk] = ci;
            nk++;
            const float4 bi4 = s_box[ci];
            const int    c   = s_cls[ci];
            const float area_i = (bi4.z - bi4.x) * (bi4.w - bi4.y);
            for (int s2 = s + 1 + lane; s2 < M; s2 += 32) {
                const int cj = s_order[s2];
                if (s_cls[cj] != c) continue;
                const float4 bj = s_box[cj];
                const float yy1 = fmaxf(bi4.x, bj.x);
                const float xx1 = fmaxf(bi4.y, bj.y);
                const float yy2 = fminf(bi4.z, bj.z);
                const float xx2 = fminf(bi4.w, bj.w);
                const float inter = fmaxf(yy2 - yy1, 0.0f) * fmaxf(xx2 - xx1, 0.0f);
                const float area_j = (bj.z - bj.x) * (bj.w - bj.y);
                const float uni = fmaxf(area_i + area_j - inter, 1e-10f);
                if (inter / uni > NMS_THRESH) s_sup[cj] = 1;
            }
            __syncwarp();   // make suppress writes visible to next iteration
        }
        if (lane == 0) sNK = nk;
    }
    __syncthreads();

    // ---- write [100, 6] output, zero padded --------------------------------
    const int nk = sNK;
    float* o = out + (size_t)b * DET_MAX * 6;
    for (int t = tid; t < DET_MAX; t += 128) {
        if (t < nk) {
            const int ci = s_klist[t];
            const float4 bb = s_box[ci];
            o[t * 6 + 0] = bb.x;
            o[t * 6 + 1] = bb.y;
            o[t * 6 + 2] = bb.z;
            o[t * 6 + 3] = bb.w;
            o[t * 6 + 4] = (float)s_cls[ci];
            o[t * 6 + 5] = s_score[ci];
        } else {
            #pragma unroll
            for (int k = 0; k < 6; ++k) o[t * 6 + k] = 0.0f;
        }
    }
}

extern "C" void kernel_launch(void* const* d_in, const int* in_sizes, int n_in,
                              void* d_out, int out_size)
{
    const float* rois   = nullptr;
    const float* probs  = nullptr;
    const float* deltas = nullptr;
    const float* window = nullptr;
    for (int i = 0; i < n_in; ++i) {
        switch (in_sizes[i]) {
            case BATCH * N_ROIS * 4:                rois   = (const float*)d_in[i]; break;
            case BATCH * N_ROIS * NUM_CLASSES:      probs  = (const float*)d_in[i]; break;
            case BATCH * N_ROIS * NUM_CLASSES * 4:  deltas = (const float*)d_in[i]; break;
            case BATCH * 4:                         window = (const float*)d_in[i]; break;
        }
    }
    det_phase1_kernel<<<dim3(BATCH, NB_Y), 1024>>>(probs);
    det_phase2_kernel<<<BATCH, 128>>>(rois, deltas, window, (float*)d_out);
}

// round 6
// speedup vs baseline: 1.7438x; 1.1233x over previous
#include <cuda_runtime.h>
#include <cuda_bf16.h>

#define BATCH       16
#define N_ROIS      1000
#define NUM_CLASSES 81
#define DET_MAX     100
#define MIN_CONF    0.7f
#define NMS_THRESH  0.3f
#define NB_Y        9              // 16*9 = 144 phase-1 blocks (~1 per SM)
#define WPB         (32 * NB_Y)    // warps per batch in phase 1 = 288
#define MASK_CAP    192            // fast bitmask-NMS path limit
#define MASK_W      3              // 192/64 words

// Device-global scratch (zero-initialized at load; phase 2 resets g_cnt so
// every graph replay sees identical initial state).
__device__ int    g_cnt[BATCH];
__device__ float4 g_boxA[BATCH * N_ROIS];   // y1,x1,y2,x2 (refined+clipped)
__device__ float4 g_boxB[BATCH * N_ROIS];   // score, cls, roi, 0

// ---------------------------------------------------------------------------
// Phase 1: warp-per-ROI argmax + (rare) refine/clip + compact to global.
// ---------------------------------------------------------------------------
__device__ __forceinline__ void reduce_and_emit(
    float v0, float v1, float v2, int r, int b, int lane,
    const float* __restrict__ rois, const float* __restrict__ deltas,
    const float* __restrict__ window)
{
    float bv = v0; int bi = lane;
    if (v1 > bv) { bv = v1; bi = lane + 32; }
    if (v2 > bv) { bv = v2; bi = lane + 64; }
    #pragma unroll
    for (int off = 16; off > 0; off >>= 1) {
        const float ov = __shfl_xor_sync(0xffffffffu, bv, off);
        const int   oi = __shfl_xor_sync(0xffffffffu, bi, off);
        if (ov > bv || (ov == bv && oi < bi)) { bv = ov; bi = oi; }
    }
    if (lane == 0 && bi > 0 && bv >= MIN_CONF) {
        const float4 d4 = *(const float4*)(deltas +
            (((size_t)b * N_ROIS + r) * NUM_CLASSES + bi) * 4);
        const float4 rb = *(const float4*)(rois + ((size_t)b * N_ROIS + r) * 4);
        const float wy1 = window[b * 4 + 0];
        const float wx1 = window[b * 4 + 1];
        const float wy2 = window[b * 4 + 2];
        const float wx2 = window[b * 4 + 3];

        float h  = rb.z - rb.x;
        float w  = rb.w - rb.y;
        float cy = rb.x + 0.5f * h + (d4.x * 0.1f) * h;
        float cx = rb.y + 0.5f * w + (d4.y * 0.1f) * w;
        h = h * expf(d4.z * 0.2f);
        w = w * expf(d4.w * 0.2f);
        float y1 = cy - 0.5f * h;
        float x1 = cx - 0.5f * w;
        float y2 = y1 + h;
        float x2 = x1 + w;
        y1 = fminf(fmaxf(y1, wy1), wy2);
        x1 = fminf(fmaxf(x1, wx1), wx2);
        y2 = fminf(fmaxf(y2, wy1), wy2);
        x2 = fminf(fmaxf(x2, wx1), wx2);

        const int slot = atomicAdd(&g_cnt[b], 1);
        g_boxA[b * N_ROIS + slot] = make_float4(y1, x1, y2, x2);
        g_boxB[b * N_ROIS + slot] = make_float4(bv, (float)bi, (float)r, 0.0f);
    }
}

__global__ __launch_bounds__(1024, 1)
void det_phase1_kernel(const float* __restrict__ probs,
                       const float* __restrict__ rois,
                       const float* __restrict__ deltas,
                       const float* __restrict__ window)
{
    const int b    = blockIdx.x;
    const int lane = threadIdx.x & 31;
    const int gw   = blockIdx.y * 32 + (threadIdx.x >> 5);   // 0..287
    const float* base = probs + (size_t)b * N_ROIS * NUM_CLASSES;

    const int r0 = gw;
    const int r1 = gw + WPB;
    const int r2 = gw + 2 * WPB;
    const int r3 = gw + 3 * WPB;
    const bool h3 = (r3 < N_ROIS);
    const bool tail = (lane < NUM_CLASSES - 64);

    // Batch all independent loads first (MLP ~12), then reduce.
    const float* p0 = base + (size_t)r0 * NUM_CLASSES;
    const float* p1 = base + (size_t)r1 * NUM_CLASSES;
    const float* p2 = base + (size_t)r2 * NUM_CLASSES;
    const float* p3 = base + (size_t)r3 * NUM_CLASSES;

    const float a0 = p0[lane];
    const float a1 = p1[lane];
    const float a2 = p2[lane];
    const float a3 = h3 ? p3[lane] : -1e30f;
    const float b0 = p0[lane + 32];
    const float b1 = p1[lane + 32];
    const float b2 = p2[lane + 32];
    const float b3 = h3 ? p3[lane + 32] : -1e30f;
    const float c0 = tail ? p0[lane + 64] : -1e30f;
    const float c1 = tail ? p1[lane + 64] : -1e30f;
    const float c2 = tail ? p2[lane + 64] : -1e30f;
    const float c3 = (h3 && tail) ? p3[lane + 64] : -1e30f;

    reduce_and_emit(a0, b0, c0, r0, b, lane, rois, deltas, window);
    reduce_and_emit(a1, b1, c1, r1, b, lane, rois, deltas, window);
    reduce_and_emit(a2, b2, c2, r2, b, lane, rois, deltas, window);
    if (h3) reduce_and_emit(a3, b3, c3, r3, b, lane, rois, deltas, window);
}

// ---------------------------------------------------------------------------
// Phase 2: sort, per-class greedy NMS (bitmask fast path), write output.
// ---------------------------------------------------------------------------
__global__ __launch_bounds__(128, 1)
void det_phase2_kernel(float* __restrict__ out)
{
    __shared__ float4             s_box[N_ROIS];
    __shared__ float              s_score[N_ROIS];
    __shared__ int                s_cls[N_ROIS];
    __shared__ int                s_roi[N_ROIS];
    __shared__ int                s_order[N_ROIS];
    __shared__ unsigned long long s_mask[MASK_CAP * MASK_W];
    __shared__ unsigned char      s_sup[N_ROIS];
    __shared__ int                s_klist[DET_MAX];
    __shared__ int                sNK;

    const int b    = blockIdx.x;
    const int tid  = threadIdx.x;
    const int lane = tid & 31;
    const int warp = tid >> 5;

    const int M = g_cnt[b];              // same address -> broadcast load

    for (int t = tid; t < M; t += 128) {
        const float4 bb = g_boxA[b * N_ROIS + t];
        const float4 sb = g_boxB[b * N_ROIS + t];
        s_box[t]   = bb;
        s_score[t] = sb.x;
        s_cls[t]   = (int)sb.y;
        s_roi[t]   = (int)sb.z;
    }
    __syncthreads();
    if (tid == 0) { g_cnt[b] = 0; sNK = 0; }   // reset for next replay

    // ---- rank sort: score desc, roi index asc ------------------------------
    for (int t = tid; t < M; t += 128) {
        const float st = s_score[t];
        const int   rt = s_roi[t];
        int rank = 0;
        for (int j = 0; j < M; ++j) {
            const float sj = s_score[j];
            if (sj > st || (sj == st && s_roi[j] < rt)) rank++;
        }
        s_order[rank] = t;
    }
    __syncthreads();

    // ---- greedy per-class NMS ----------------------------------------------
    // Early stop at 100 kept is exact (per-class cap can't bind first; kept
    // boxes past 100 only suppress never-output lower-scored boxes).
    if (M <= MASK_CAP) {
        // Fast path: parallel suppression-bitmask precompute, scalar greedy.
        for (int s = tid; s < M; s += 128) {
            const int    ci  = s_order[s];
            const float4 bi4 = s_box[ci];
            const int    c   = s_cls[ci];
            const float  area_i = (bi4.z - bi4.x) * (bi4.w - bi4.y);
            unsigned long long m0 = 0, m1 = 0, m2 = 0;
            for (int j = s + 1; j < M; ++j) {
                const int cj = s_order[j];
                if (s_cls[cj] != c) continue;
                const float4 bj = s_box[cj];
                const float yy1 = fmaxf(bi4.x, bj.x);
                const float xx1 = fmaxf(bi4.y, bj.y);
                const float yy2 = fminf(bi4.z, bj.z);
                const float xx2 = fminf(bi4.w, bj.w);
                const float inter = fmaxf(yy2 - yy1, 0.0f) * fmaxf(xx2 - xx1, 0.0f);
                const float area_j = (bj.z - bj.x) * (bj.w - bj.y);
                const float uni = fmaxf(area_i + area_j - inter, 1e-10f);
                if (inter / uni > NMS_THRESH) {
                    const unsigned long long bit = 1ull << (j & 63);
                    if      ((j >> 6) == 0) m0 |= bit;
                    else if ((j >> 6) == 1) m1 |= bit;
                    else                    m2 |= bit;
                }
            }
            s_mask[s * MASK_W + 0] = m0;
            s_mask[s * MASK_W + 1] = m1;
            s_mask[s * MASK_W + 2] = m2;
        }
        __syncthreads();
        if (tid == 0) {
            unsigned long long a0 = ~0ull, a1 = ~0ull, a2 = ~0ull;
            int nk = 0;
            for (int s = 0; s < M && nk < DET_MAX; ++s) {
                const unsigned long long aw = (s >> 6) == 0 ? a0 : ((s >> 6) == 1 ? a1 : a2);
                if ((aw >> (s & 63)) & 1ull) {
                    s_klist[nk++] = s_order[s];
                    a0 &= ~s_mask[s * MASK_W + 0];
                    a1 &= ~s_mask[s * MASK_W + 1];
                    a2 &= ~s_mask[s * MASK_W + 2];
                }
            }
            sNK = nk;
        }
        __syncthreads();
    } else {
        // Fallback: warp-greedy (correct for any M up to N_ROIS).
        for (int t = tid; t < M; t += 128) s_sup[t] = 0;
        __syncthreads();
        if (warp == 0) {
            int nk = 0;
            for (int s = 0; s < M && nk < DET_MAX; ++s) {
                const int ci = s_order[s];
                if (s_sup[ci]) continue;
                if (lane == 0) s_klist[nk] = ci;
                nk++;
                const float4 bi4 = s_box[ci];
                const int    c   = s_cls[ci];
                const float area_i = (bi4.z - bi4.x) * (bi4.w - bi4.y);
                for (int s2 = s + 1 + lane; s2 < M; s2 += 32) {
                    const int cj = s_order[s2];
                    if (s_cls[cj] != c) continue;
                    const float4 bj = s_box[cj];
                    const float yy1 = fmaxf(bi4.x, bj.x);
                    const float xx1 = fmaxf(bi4.y, bj.y);
                    const float yy2 = fminf(bi4.z, bj.z);
                    const float xx2 = fminf(bi4.w, bj.w);
                    const float inter = fmaxf(yy2 - yy1, 0.0f) * fmaxf(xx2 - xx1, 0.0f);
                    const float area_j = (bj.z - bj.x) * (bj.w - bj.y);
                    const float uni = fmaxf(area_i + area_j - inter, 1e-10f);
                    if (inter / uni > NMS_THRESH) s_sup[cj] = 1;
                }
                __syncwarp();
            }
            if (lane == 0) sNK = nk;
        }
        __syncthreads();
    }

    // ---- write [100, 6] output, zero padded --------------------------------
    const int nk = sNK;
    float* o = out + (size_t)b * DET_MAX * 6;
    for (int t = tid; t < DET_MAX; t += 128) {
        if (t < nk) {
            const int ci = s_klist[t];
            const float4 bb = s_box[ci];
            o[t * 6 + 0] = bb.x;
            o[t * 6 + 1] = bb.y;
            o[t * 6 + 2] = bb.z;
            o[t * 6 + 3] = bb.w;
            o[t * 6 + 4] = (float)s_cls[ci];
            o[t * 6 + 5] = s_score[ci];
        } else {
            #pragma unroll
            for (int k = 0; k < 6; ++k) o[t * 6 + k] = 0.0f;
        }
    }
}

extern "C" void kernel_launch(void* const* d_in, const int* in_sizes, int n_in,
                              void* d_out, int out_size)
{
    const float* rois   = nullptr;
    const float* probs  = nullptr;
    const float* deltas = nullptr;
    const float* window = nullptr;
    for (int i = 0; i < n_in; ++i) {
        switch (in_sizes[i]) {
            case BATCH * N_ROIS * 4:                rois   = (const float*)d_in[i]; break;
            case BATCH * N_ROIS * NUM_CLASSES:      probs  = (const float*)d_in[i]; break;
            case BATCH * N_ROIS * NUM_CLASSES * 4:  deltas = (const float*)d_in[i]; break;
            case BATCH * 4:                         window = (const float*)d_in[i]; break;
        }
    }
    det_phase1_kernel<<<dim3(BATCH, NB_Y), 1024>>>(probs, rois, deltas, window);
    det_phase2_kernel<<<BATCH, 128>>>((float*)d_out);
}